// round 13
// baseline (speedup 1.0000x reference)
#include <cuda_runtime.h>
#include <math.h>

#define V_NODES 50000
#define E_EDGES 25000
#define NNZ     600000
#define NSUB    8
#define KDIM    16
#define D       128          // NSUB*KDIM
#define NUM_STEP 4
#define EPSF    1e-10f

#define NB      2048         // gather grid blocks

// ---------------- persistent device scratch (no allocations allowed) ----------
static __device__ float g_Xbuf[(size_t)V_NODES * D];   // current X (prob values)
static __device__ float g_Yval[(size_t)E_EDGES * D];   // current Y (mean values)
static __device__ int   g_adjE[NNZ];                   // per-edge adjacency: node ids
static __device__ int   g_adjV[NNZ];                   // per-node adjacency: edge ids
static __device__ int   g_offE[E_EDGES];
static __device__ int   g_offV[V_NODES];
static __device__ int   g_curE[E_EDGES];
static __device__ int   g_curV[V_NODES];
static __device__ int   g_cntE[E_EDGES];
static __device__ int   g_cntV[V_NODES];
static __device__ float g_invCntE[E_EDGES];
static __device__ float g_invCntV[V_NODES];
static __device__ int   g_cursorE;
static __device__ int   g_cursorV;
static __device__ int   g_done;
static __device__ float g_pAcc[D];
static __device__ float g_sqAcc[D];
static __device__ float g_gram[D * KDIM];
static __device__ float g_ent;
static __device__ float g_lossLocal;
static __device__ float g_lossGlobal;

// ---------------- init: zero counts + cursors + stats + losses ----------------
__global__ void k_init() {
    int i = blockIdx.x * blockDim.x + threadIdx.x;
    int stride = gridDim.x * blockDim.x;
    for (int j = i; j < E_EDGES; j += stride) g_cntE[j] = 0;
    for (int j = i; j < V_NODES; j += stride) g_cntV[j] = 0;
    if (i < D) { g_pAcc[i] = 0.f; g_sqAcc[i] = 0.f; }
    if (i < D * KDIM) g_gram[i] = 0.f;
    if (i == 0) {
        g_ent = 0.f; g_lossLocal = 0.f; g_lossGlobal = 0.f;
        g_cursorE = 0; g_cursorV = 0; g_done = 0;
    }
}

// ---------------- degree counts (step-invariant) ----------------
__global__ void k_counts(const int* __restrict__ Vi, const int* __restrict__ Ei) {
    int i = blockIdx.x * blockDim.x + threadIdx.x;
    if (i < NNZ) {
        atomicAdd(&g_cntE[Ei[i]], 1);
        atomicAdd(&g_cntV[Vi[i]], 1);
    }
}

// ---------------- offsets via atomic cursor (CSR placement order is free) -----
__global__ void k_offsets() {
    int i = blockIdx.x * blockDim.x + threadIdx.x;
    if (i < E_EDGES) {
        int c = g_cntE[i];
        int o = atomicAdd(&g_cursorE, c);
        g_offE[i] = o; g_curE[i] = o;
        g_invCntE[i] = 1.f / fmaxf((float)c, 1.f);
    }
    if (i < V_NODES) {
        int c = g_cntV[i];
        int o = atomicAdd(&g_cursorV, c);
        g_offV[i] = o; g_curV[i] = o;
        g_invCntV[i] = 1.f / fmaxf((float)c, 1.f);
    }
}

// ---------------- CSR fill ----------------
__global__ void k_fill(const int* __restrict__ Vi, const int* __restrict__ Ei) {
    int i = blockIdx.x * blockDim.x + threadIdx.x;
    if (i >= NNZ) return;
    int v = Vi[i], e = Ei[i];
    int pe = atomicAdd(&g_curE[e], 1);
    g_adjE[pe] = v;
    int pv = atomicAdd(&g_curV[v], 1);
    g_adjV[pv] = e;
}

// ---------------- gumbel softmax: X0 = softmax(logits + gumbel) over K ----------
__global__ void k_gumbel(const float* __restrict__ emb, const float* __restrict__ gum) {
    int v = blockIdx.x;
    int t = threadIdx.x;                 // (s = t/16, k = t%16)
    size_t off = (size_t)v * D + t;
    float x = emb[off] + gum[off];       // TAU == 1
    float m = x;
    #pragma unroll
    for (int o = 8; o >= 1; o >>= 1) m = fmaxf(m, __shfl_xor_sync(0xFFFFFFFFu, m, o, 16));
    float e = __expf(x - m);
    float ssum = e;
    #pragma unroll
    for (int o = 8; o >= 1; o >>= 1) ssum += __shfl_xor_sync(0xFFFFFFFFu, ssum, o, 16);
    g_Xbuf[off] = e / ssum;
}

// ---------------- fused gather + mean + stats + (last block) finalize ----------
// Block of 128 threads, thread t owns column (s = t/16, i = t%16).
// IS_X=false: Y[e] = mean over incident nodes of X   (E rows)
// IS_X=true : X[v] = mean over incident edges of Y   (V rows)
// Stats accumulate via float atomics; the last block (threadfence+ticket)
// folds stats into the two losses and re-zeros everything for the next call.
template <bool IS_X>
__global__ void __launch_bounds__(128) k_gather() {
    const int nrows = IS_X ? V_NODES : E_EDGES;
    const int* __restrict__ adj    = IS_X ? g_adjV : g_adjE;
    const int* __restrict__ off    = IS_X ? g_offV : g_offE;
    const int* __restrict__ cnt    = IS_X ? g_cntV : g_cntE;
    const float* __restrict__ invc = IS_X ? g_invCntV : g_invCntE;
    const float* __restrict__ src  = IS_X ? g_Yval : g_Xbuf;
    float* __restrict__ dst        = IS_X ? g_Xbuf : g_Yval;

    __shared__ float shA[D], shB[D];
    __shared__ int s_ticket;
    int t = threadIdx.x, lane = t & 31, base = lane & 16;
    float pacc = 0.f, sqacc = 0.f, ent = 0.f;
    float gacc[KDIM];
    #pragma unroll
    for (int j = 0; j < KDIM; j++) gacc[j] = 0.f;

    for (int r = blockIdx.x; r < nrows; r += NB) {
        int o = off[r], c = cnt[r];
        float a0 = 0.f, a1 = 0.f, a2 = 0.f, a3 = 0.f;
        int j = 0;
        for (; j + 4 <= c; j += 4) {
            int i0 = adj[o + j], i1 = adj[o + j + 1];
            int i2 = adj[o + j + 2], i3 = adj[o + j + 3];
            a0 += src[(size_t)i0 * D + t];
            a1 += src[(size_t)i1 * D + t];
            a2 += src[(size_t)i2 * D + t];
            a3 += src[(size_t)i3 * D + t];
        }
        for (; j < c; j++) a0 += src[(size_t)adj[o + j] * D + t];
        float y = ((a0 + a1) + (a2 + a3)) * invc[r];
        dst[(size_t)r * D + t] = y;
        ent   += y * __logf(y + EPSF);
        pacc  += y;
        sqacc += y * y;
        #pragma unroll
        for (int j2 = 0; j2 < KDIM; j2++)
            gacc[j2] += y * __shfl_sync(0xFFFFFFFFu, y, base + j2, 32);
    }

    // stat accumulation (float atomics; per-address chains ~NB deep, parallel
    // across the 2308 distinct addresses -> ~1us)
    atomicAdd(&g_pAcc[t], pacc);
    atomicAdd(&g_sqAcc[t], sqacc);
    #pragma unroll
    for (int j2 = 0; j2 < KDIM; j2++) atomicAdd(&g_gram[t * KDIM + j2], gacc[j2]);
    #pragma unroll
    for (int o2 = 16; o2 >= 1; o2 >>= 1)
        ent += __shfl_xor_sync(0xFFFFFFFFu, ent, o2);
    if (lane == 0) atomicAdd(&g_ent, ent);

    // last-block finalize
    __threadfence();
    __syncthreads();
    if (t == 0) s_ticket = atomicAdd(&g_done, 1);
    __syncthreads();
    if (s_ticket != NB - 1) return;
    __threadfence();

    float invN = 1.f / (float)nrows;
    float p = g_pAcc[t] * invN;
    float plogp = p * __logf(p + EPSF);

    float ni = sqrtf(g_sqAcc[t]);
    float Crow[KDIM];
    float mx = -1e30f;
    #pragma unroll
    for (int j2 = 0; j2 < KDIM; j2++) {
        float nj = __shfl_sync(0xFFFFFFFFu, ni, base + j2, 32);
        float c = g_gram[t * KDIM + j2] / fmaxf(ni * nj, EPSF);
        Crow[j2] = c;
        mx = fmaxf(mx, c);
    }
    float se = 0.f;
    #pragma unroll
    for (int j2 = 0; j2 < KDIM; j2++) se += __expf(Crow[j2] - mx);
    float nld = mx + __logf(se) - Crow[t & 15];    // -log(softmax diag)

    shA[t] = plogp; shB[t] = nld;
    __syncthreads();
    #pragma unroll
    for (int s2 = 64; s2 >= 1; s2 >>= 1) {
        if (t < s2) { shA[t] += shA[t + s2]; shB[t] += shB[t + s2]; }
        __syncthreads();
    }
    if (t == 0) {
        // loss_global += -mean_S(-sum_k p log(p+eps)) + discrimination
        g_lossGlobal += shA[0] / (float)NSUB + shB[0] / (float)D;
        // loss_local += mean over (N,S) of -sum_k y log(y+eps)
        g_lossLocal  += -g_ent / ((float)nrows * (float)NSUB);
        g_ent = 0.f;
        g_done = 0;
    }
    // re-zero stats for the next gather invocation
    g_pAcc[t] = 0.f;
    g_sqAcc[t] = 0.f;
    #pragma unroll
    for (int j2 = 0; j2 < KDIM; j2++) g_gram[t * KDIM + j2] = 0.f;
}

// ---------------- output ----------------
__global__ void k_out(float* __restrict__ out, int n) {
    int i = blockIdx.x * blockDim.x + threadIdx.x;
    if (i >= n) return;
    float v = 0.f;
    if (i == 0) v = g_lossLocal;
    else if (i == 1) v = g_lossGlobal;
    out[i] = v;
}

// ---------------- launch ----------------
extern "C" void kernel_launch(void* const* d_in, const int* in_sizes, int n_in,
                              void* d_out, int out_size) {
    const float* emb = (const float*)d_in[0];
    const float* gum = (const float*)d_in[1];
    const int*   Vi  = (const int*)d_in[2];
    const int*   Ei  = (const int*)d_in[3];
    float* out = (float*)d_out;

    k_init<<<512, 256>>>();                                    // launch 1
    k_counts<<<(NNZ + 255) / 256, 256>>>(Vi, Ei);              // launch 2
    k_offsets<<<(V_NODES + 255) / 256, 256>>>();               // launch 3
    k_fill<<<(NNZ + 255) / 256, 256>>>(Vi, Ei);                // launch 4
    k_gumbel<<<V_NODES, 128>>>(emb, gum);                      // launch 5

    for (int step = 0; step < NUM_STEP; step++) {
        k_gather<false><<<NB, 128>>>();                        // launch 6 = profiled
        k_gather<true><<<NB, 128>>>();
    }
    k_out<<<1, 256>>>(out, out_size);
}